// round 11
// baseline (speedup 1.0000x reference)
#include <cuda_runtime.h>
#include <stdint.h>

// Problem shape (fixed by the reference): x is (T, B, 1) fp32, lr scalar.
#define T_DIM 8192
#define B_DIM 4096
#define S_CHUNKS 64
#define HALF (S_CHUNKS / 2)   // 32 chunks per half
#define CH 128                // T_DIM / S_CHUNKS
#define NWORDS 4              // CH / 32

// Scratch (device globals). Chunk-major, coalesced over b.
__device__ float4 g_coef [S_CHUNKS * B_DIM];        // (A0,C0,A1,C1)       4 MB
__device__ uint4  g_bits [S_CHUNKS * B_DIM];        // 128 packed x bits   4 MB
__device__ float  g_xprev[S_CHUNKS * B_DIM];        // x[t0-1]             1 MB
__device__ float2 g_state[(S_CHUNKS + 1) * B_DIM];  // entry (p0,p1); +1 for hand-off

__device__ __forceinline__ float clamp_lr(const float* lrp) {
    return fminf(fmaxf(*lrp, 0.0f), 1.0f);
}

// r^n, n in [0,128], square-and-multiply (no smem, no syncs).
__device__ __forceinline__ float rpow_int(float r, int n) {
    float res = 1.0f, base = r;
    #pragma unroll
    for (int i = 0; i < 8; i++) {
        res  = ((n >> i) & 1) ? res * base : res;
        base = base * base;
    }
    return res;
}

// ---------------------------------------------------------------------------
// Pass-1 body (R4 math, plain LDG — __ldcs reverted per R10 measurement):
// stream one x chunk, pack bits, emit affine (A,C) via the popcount trick.
// ---------------------------------------------------------------------------
__device__ __forceinline__ void pass1_body(
    const float* __restrict__ x, float lr, float r, int s, int b)
{
    const float* xp = x + (size_t)(s * CH) * B_DIM + b;

    const float xprev = (s == 0) ? 0.0f : xp[-(ptrdiff_t)B_DIM];
    g_xprev[s * B_DIM + b] = xprev;
    bool pb = (xprev != 0.0f);

    float C0 = 0.0f, C1 = 0.0f;
    uint32_t W[NWORDS];

    #pragma unroll
    for (int h = 0; h < NWORDS; h++) {
        uint32_t w = 0;
        #pragma unroll
        for (int i0 = 0; i0 < 32; i0 += 8) {
            float xv[8];                               // 8-deep LDG batch
            #pragma unroll
            for (int j = 0; j < 8; j++)
                xv[j] = xp[(size_t)(h * 32 + i0 + j) * B_DIM];
            #pragma unroll
            for (int j = 0; j < 8; j++) {
                const float v  = xv[j];
                const bool  xb = (v != 0.0f);
                const float t  = v * lr;               // exact: x in {0,1}
                C0 = pb ? C0 : fmaf(C0, r, t);
                C1 = pb ? fmaf(C1, r, t) : C1;
                w  = xb ? (w | (1u << (i0 + j))) : w;
                pb = xb;
            }
        }
        W[h] = w;
    }

    const int ones = __popc(W[0]) + __popc(W[1]) + __popc(W[2]) + __popc(W[3]);
    const int n1   = ones - (int)(W[3] >> 31) + (xprev != 0.0f ? 1 : 0);

    g_coef[s * B_DIM + b] = make_float4(rpow_int(r, CH - n1), C0,
                                        rpow_int(r, n1),      C1);
    g_bits[s * B_DIM + b] = make_uint4(W[0], W[1], W[2], W[3]);
}

// ---------------------------------------------------------------------------
// Pass-2 body (R10 lean step — proven win): selected/other representation,
// ~7 instructions per output including the store.
// ---------------------------------------------------------------------------
__device__ __forceinline__ void pass2_body(
    float* __restrict__ out, float lr, float r, int s, int b)
{
    float* op = out + (size_t)(s * CH) * B_DIM + b;

    const float2 st = g_state[s * B_DIM + b];
    const uint4  bw = g_bits [s * B_DIM + b];
    const uint32_t W[NWORDS] = { bw.x, bw.y, bw.z, bw.w };
    bool pb = (g_xprev[s * B_DIM + b] != 0.0f);

    float pa = pb ? st.y : st.x;     // selected lineage
    float po = pb ? st.x : st.y;     // other lineage

    #pragma unroll
    for (int wi = 0; wi < NWORDS; wi++) {
        const uint32_t w = W[wi];
        #pragma unroll
        for (int i = 0; i < 32; i++) {
            const bool  xb  = (w >> i) & 1u;
            const float add = xb ? lr : 0.0f;
            const float u   = fmaf(r, pa, add);
            const bool  sw  = (xb == pb);
            const float npa = sw ? u  : po;
            po              = sw ? po : u;
            pa = npa;
            op[(size_t)(wi * 32 + i) * B_DIM] = pa;   // output == next selected
            pb = xb;
        }
    }
}

// ---------------------------------------------------------------------------
// Stage kernels.
// ---------------------------------------------------------------------------
__global__ void __launch_bounds__(256) p1_kernel(
    const float* __restrict__ x, const float* __restrict__ lrp, int s_base)
{
    const int b = blockIdx.x * blockDim.x + threadIdx.x;
    const float lr = clamp_lr(lrp);
    pass1_body(x, lr, 1.0f - lr, s_base + blockIdx.y, b);
}

__global__ void __launch_bounds__(256) p2_kernel(
    float* __restrict__ out, const float* __restrict__ lrp, int s_base)
{
    const int b = blockIdx.x * blockDim.x + threadIdx.x;
    const float lr = clamp_lr(lrp);
    pass2_body(out, lr, 1.0f - lr, s_base + blockIdx.y, b);
}

// Mixed grid: even blockIdx.y -> pass2 on H1 chunk y/2 (writes),
//             odd  blockIdx.y -> pass1 on H2 chunk 32+y/2 (reads).
// Interleaved dispatch keeps both HBM directions active simultaneously.
__global__ void __launch_bounds__(256) mixed_kernel(
    const float* __restrict__ x, float* __restrict__ out,
    const float* __restrict__ lrp)
{
    const int b = blockIdx.x * blockDim.x + threadIdx.x;
    const float lr = clamp_lr(lrp);
    const float r  = 1.0f - lr;
    const int y = blockIdx.y;
    if (y & 1) pass1_body(x, lr, r, HALF + (y >> 1), b);
    else       pass2_body(out, lr, r, (y >> 1), b);
}

// Partial scan over chunks [s_begin, s_end): stores entry state per chunk and
// the hand-off entry at s_end. init=1 -> start from (0.5, 0.5), else resume
// from the stored hand-off at s_begin.
__global__ void __launch_bounds__(256) scan_kernel(int s_begin, int s_end, int init)
{
    const int b = blockIdx.x * blockDim.x + threadIdx.x;
    float p0, p1;
    if (init) { p0 = 0.5f; p1 = 0.5f; }
    else      { const float2 h = g_state[s_begin * B_DIM + b]; p0 = h.x; p1 = h.y; }

    #pragma unroll 8
    for (int s = s_begin; s < s_end; s++) {
        g_state[s * B_DIM + b] = make_float2(p0, p1);
        const float4 c = g_coef[s * B_DIM + b];
        p0 = fmaf(p0, c.x, c.y);
        p1 = fmaf(p1, c.z, c.w);
    }
    g_state[s_end * B_DIM + b] = make_float2(p0, p1);   // hand-off
}

extern "C" void kernel_launch(void* const* d_in, const int* in_sizes, int n_in,
                              void* d_out, int out_size)
{
    const float* x  = (const float*)d_in[0];
    const float* lr = (const float*)d_in[1];
    if (n_in >= 2 && in_sizes[0] == 1) { x = (const float*)d_in[1]; lr = (const float*)d_in[0]; }
    float* out = (float*)d_out;

    dim3 blk(256);
    dim3 grid_half (B_DIM / 256, HALF);       // (16, 32)
    dim3 grid_mixed(B_DIM / 256, S_CHUNKS);   // (16, 64): 512 p2 + 512 p1 blocks

    p1_kernel  <<<grid_half,  blk>>>(x, lr, 0);          // read H1
    scan_kernel<<<B_DIM / 256, blk>>>(0, HALF, 1);       // states 0..31 + hand-off
    mixed_kernel<<<grid_mixed, blk>>>(x, out, lr);       // write H1 || read H2
    scan_kernel<<<B_DIM / 256, blk>>>(HALF, S_CHUNKS, 0);// states 32..63
    p2_kernel  <<<grid_half,  blk>>>(out, lr, HALF);     // write H2
}